// round 1
// baseline (speedup 1.0000x reference)
#include <cuda_runtime.h>
#include <cuda_bf16.h>

#define N_NODES 100000
#define F_IN    512
#define HID     64
#define NCLS    64

// Scratch for intermediate logits [N_NODES, 64] (no runtime allocation allowed).
__device__ float g_logits[(size_t)N_NODES * NCLS];

// ---------------------------------------------------------------------------
// Fused MLP: logits = relu(X @ W1 + b1) @ W2 + b2
// Block: 64 rows of X. 256 threads, each computes 4x4 outputs.
// ---------------------------------------------------------------------------
__global__ __launch_bounds__(256) void mlp_fused(
    const float* __restrict__ X,
    const float* __restrict__ W1,
    const float* __restrict__ b1,
    const float* __restrict__ W2,
    const float* __restrict__ b2)
{
    __shared__ float Xs[32][64];    // [k][m] transposed X tile
    __shared__ float Ws[32][64];    // [k][n] W1 tile
    __shared__ float Hst[64][68];   // [k2 = hidden][m] transposed hidden acts
    __shared__ float W2s[64][68];   // [k2][n2]

    const int t  = threadIdx.x;
    const int tx = t & 15;          // output col group (n)
    const int ty = t >> 4;          // output row group (m)
    const int rb = blockIdx.x * 64;

    float acc[4][4];
#pragma unroll
    for (int i = 0; i < 4; i++)
#pragma unroll
        for (int j = 0; j < 4; j++) acc[i][j] = 0.0f;

    for (int k0 = 0; k0 < F_IN; k0 += 32) {
        // Load X tile 64 rows x 32 k (coalesced float4, store transposed)
#pragma unroll
        for (int l = 0; l < 2; l++) {
            int idx = t + l * 256;
            int m   = idx >> 3;          // 0..63
            int c4  = (idx & 7) * 4;     // k offset 0..28
            float4 v = make_float4(0.f, 0.f, 0.f, 0.f);
            int grow = rb + m;
            if (grow < N_NODES)
                v = *(const float4*)(X + (size_t)grow * F_IN + k0 + c4);
            Xs[c4 + 0][m] = v.x;
            Xs[c4 + 1][m] = v.y;
            Xs[c4 + 2][m] = v.z;
            Xs[c4 + 3][m] = v.w;
        }
        // Load W1 tile 32 k x 64 n
#pragma unroll
        for (int l = 0; l < 2; l++) {
            int idx = t + l * 256;
            int kr  = idx >> 4;          // 0..31
            int c4  = (idx & 15) * 4;    // 0..60
            *(float4*)&Ws[kr][c4] =
                *(const float4*)(W1 + (size_t)(k0 + kr) * HID + c4);
        }
        __syncthreads();

#pragma unroll
        for (int k = 0; k < 32; k++) {
            float a[4], b[4];
            *(float4*)a = *(const float4*)&Xs[k][ty * 4];
            *(float4*)b = *(const float4*)&Ws[k][tx * 4];
#pragma unroll
            for (int i = 0; i < 4; i++)
#pragma unroll
                for (int j = 0; j < 4; j++)
                    acc[i][j] = fmaf(a[i], b[j], acc[i][j]);
        }
        __syncthreads();
    }

    // bias + relu, write transposed hidden tile Hst[k2][m]
#pragma unroll
    for (int j = 0; j < 4; j++) {
        float bj = b1[tx * 4 + j];
#pragma unroll
        for (int i = 0; i < 4; i++) {
            float h = acc[i][j] + bj;
            h = h > 0.0f ? h : 0.0f;
            Hst[tx * 4 + j][ty * 4 + i] = h;
        }
    }
    // Load W2 (64x64) into SMEM
#pragma unroll
    for (int l = 0; l < 4; l++) {
        int idx = t + l * 256;
        int kr  = idx >> 4;          // 0..63
        int c4  = (idx & 15) * 4;
        *(float4*)&W2s[kr][c4] = *(const float4*)(W2 + (size_t)kr * NCLS + c4);
    }
    __syncthreads();

    float acc2[4][4];
#pragma unroll
    for (int i = 0; i < 4; i++)
#pragma unroll
        for (int j = 0; j < 4; j++) acc2[i][j] = 0.0f;

#pragma unroll
    for (int k = 0; k < HID; k++) {
        float a[4], b[4];
        *(float4*)a = *(const float4*)&Hst[k][ty * 4];
        *(float4*)b = *(const float4*)&W2s[k][tx * 4];
#pragma unroll
        for (int i = 0; i < 4; i++)
#pragma unroll
            for (int j = 0; j < 4; j++)
                acc2[i][j] = fmaf(a[i], b[j], acc2[i][j]);
    }

    // + b2, store logits
    float bb[4];
    *(float4*)bb = *(const float4*)(b2 + tx * 4);
#pragma unroll
    for (int i = 0; i < 4; i++) {
        int grow = rb + ty * 4 + i;
        if (grow < N_NODES) {
            float4 o;
            o.x = acc2[i][0] + bb[0];
            o.y = acc2[i][1] + bb[1];
            o.z = acc2[i][2] + bb[2];
            o.w = acc2[i][3] + bb[3];
            *(float4*)(g_logits + (size_t)grow * NCLS + tx * 4) = o;
        }
    }
}

// ---------------------------------------------------------------------------
// Edge scatter: out[row] += val * logits[col]
// 16 threads per edge, float4 gather + vectorized red.global.add.v4.f32
// ---------------------------------------------------------------------------
__global__ __launch_bounds__(256) void edge_scatter(
    const int*   __restrict__ rows,
    const int*   __restrict__ cols,
    const float* __restrict__ vals,
    float*       __restrict__ out,
    int E)
{
    long long tid = (long long)blockIdx.x * 256 + threadIdx.x;
    int e = (int)(tid >> 4);
    if (e >= E) return;
    int j = (int)(tid & 15);

    int   r = rows[e];
    int   c = cols[e];
    float v = vals[e];

    const float4* lrow = (const float4*)(g_logits + (size_t)c * NCLS);
    float4 m = lrow[j];
    m.x *= v; m.y *= v; m.z *= v; m.w *= v;

    float* dst = out + (size_t)r * NCLS + j * 4;
    asm volatile("red.global.add.v4.f32 [%0], {%1, %2, %3, %4};"
                 :: "l"(dst), "f"(m.x), "f"(m.y), "f"(m.z), "f"(m.w)
                 : "memory");
}

// ---------------------------------------------------------------------------
extern "C" void kernel_launch(void* const* d_in, const int* in_sizes, int n_in,
                              void* d_out, int out_size)
{
    const float* X    = (const float*)d_in[0];
    const int*   erow = (const int*)  d_in[1];
    const int*   ecol = (const int*)  d_in[2];
    const float* ev   = (const float*)d_in[3];
    const float* W1   = (const float*)d_in[4];
    const float* b1   = (const float*)d_in[5];
    const float* W2   = (const float*)d_in[6];
    const float* b2   = (const float*)d_in[7];
    float* out = (float*)d_out;
    int E = in_sizes[1];

    cudaMemsetAsync(d_out, 0, (size_t)out_size * sizeof(float));

    mlp_fused<<<(N_NODES + 63) / 64, 256>>>(X, W1, b1, W2, b2);

    long long threads = (long long)E * 16;
    int blocks = (int)((threads + 255) / 256);
    edge_scatter<<<blocks, 256>>>(erow, ecol, ev, out, E);
}

// round 3
// speedup vs baseline: 1.1746x; 1.1746x over previous
#include <cuda_runtime.h>
#include <cuda_fp16.h>
#include <stdint.h>

#define N_NODES 100000
#define F_IN    512
#define HID     64
#define NCLS    64
#define BM      128

// fp16 logits scratch (halves scatter gather traffic). 12.8 MB.
__device__ __align__(16) __half g_logits_h[(size_t)N_NODES * NCLS];

__device__ __forceinline__ uint32_t f2tf32(float f) {
    uint32_t o; asm("cvt.rna.tf32.f32 %0, %1;" : "=r"(o) : "f"(f)); return o;
}
__device__ __forceinline__ void mma_tf32(float* c, const uint32_t* a, const uint32_t* b) {
    asm volatile("mma.sync.aligned.m16n8k8.row.col.f32.tf32.tf32.f32 "
        "{%0,%1,%2,%3}, {%4,%5,%6,%7}, {%8,%9}, {%0,%1,%2,%3};\n"
        : "+f"(c[0]), "+f"(c[1]), "+f"(c[2]), "+f"(c[3])
        : "r"(a[0]), "r"(a[1]), "r"(a[2]), "r"(a[3]), "r"(b[0]), "r"(b[1]));
}
__device__ __forceinline__ void mma_f16(float* c, const uint32_t* a, const uint32_t* b) {
    asm volatile("mma.sync.aligned.m16n8k16.row.col.f32.f16.f16.f32 "
        "{%0,%1,%2,%3}, {%4,%5,%6,%7}, {%8,%9}, {%0,%1,%2,%3};\n"
        : "+f"(c[0]), "+f"(c[1]), "+f"(c[2]), "+f"(c[3])
        : "r"(a[0]), "r"(a[1]), "r"(a[2]), "r"(a[3]), "r"(b[0]), "r"(b[1]));
}

// ---------------------------------------------------------------------------
// Fused MLP on tensor cores:
//   h = relu(X @ W1 + b1)  -> tf32 mma, fp32 accum
//   logits = h @ W2 + b2   -> f16 mma, fp32 accum, stored fp16
// Block: 128 rows, 8 warps in a 4(M) x 2(N) grid; warp tile 32x32.
// ---------------------------------------------------------------------------
__global__ __launch_bounds__(256) void mlp_mma(
    const float* __restrict__ X,
    const float* __restrict__ W1,
    const float* __restrict__ b1,
    const float* __restrict__ W2,
    const float* __restrict__ b2)
{
    // 27648 bytes total; phase-2 arrays overlay phase-1 arrays.
    __shared__ __align__(16) uint32_t smem[6912];
    uint32_t (*Xs)[36]  = (uint32_t(*)[36])smem;           // tf32 [128][36]
    uint32_t (*Ws)[72]  = (uint32_t(*)[72])(smem + 4608);  // tf32 [32][72]
    uint32_t (*H2)[36]  = (uint32_t(*)[36])smem;           // half2 [128][36] (k-pairs)
    uint32_t (*W2p)[72] = (uint32_t(*)[72])(smem + 4608);  // half2 [32][72]  (k-pairs)

    const int t    = threadIdx.x;
    const int lane = t & 31;
    const int wid  = t >> 5;
    const int wm   = wid & 3;     // warp M index (rows 32*wm)
    const int wn   = wid >> 2;    // warp N index (cols 32*wn)
    const int g    = lane >> 2;   // 0..7
    const int tq   = lane & 3;    // 0..3
    const int rb   = blockIdx.x * BM;

    float c1[2][4][4];
#pragma unroll
    for (int m = 0; m < 2; m++)
#pragma unroll
        for (int n = 0; n < 4; n++)
#pragma unroll
            for (int i = 0; i < 4; i++) c1[m][n][i] = 0.0f;

    for (int cc = 0; cc < F_IN / 32; cc++) {
        const int kb = cc * 32;
        // X tile: 128 rows x 32 k = 1024 float4; 4 per thread, convert to tf32
#pragma unroll
        for (int l = 0; l < 4; l++) {
            int idx = t + l * 256;
            int row = idx >> 3;
            int c4  = (idx & 7) * 4;
            float4 v = make_float4(0.f, 0.f, 0.f, 0.f);
            int grow = rb + row;
            if (grow < N_NODES)
                v = *(const float4*)(X + (size_t)grow * F_IN + kb + c4);
            uint4 u;
            u.x = f2tf32(v.x); u.y = f2tf32(v.y); u.z = f2tf32(v.z); u.w = f2tf32(v.w);
            *(uint4*)&Xs[row][c4] = u;
        }
        // W1 tile: 32 k x 64 n = 512 float4; 2 per thread
#pragma unroll
        for (int l = 0; l < 2; l++) {
            int idx = t + l * 256;
            int kr  = idx >> 4;
            int c4  = (idx & 15) * 4;
            float4 v = *(const float4*)(W1 + (size_t)(kb + kr) * HID + c4);
            uint4 u;
            u.x = f2tf32(v.x); u.y = f2tf32(v.y); u.z = f2tf32(v.z); u.w = f2tf32(v.w);
            *(uint4*)&Ws[kr][c4] = u;
        }
        __syncthreads();

#pragma unroll
        for (int ka = 0; ka < 4; ka++) {
            const int k0 = ka * 8;
            uint32_t a[2][4];
#pragma unroll
            for (int m = 0; m < 2; m++) {
                int row = wm * 32 + m * 16;
                a[m][0] = Xs[row + g    ][k0 + tq];
                a[m][1] = Xs[row + g + 8][k0 + tq];
                a[m][2] = Xs[row + g    ][k0 + tq + 4];
                a[m][3] = Xs[row + g + 8][k0 + tq + 4];
            }
            uint32_t b[4][2];
#pragma unroll
            for (int n = 0; n < 4; n++) {
                int col = wn * 32 + n * 8 + g;
                b[n][0] = Ws[k0 + tq    ][col];
                b[n][1] = Ws[k0 + tq + 4][col];
            }
#pragma unroll
            for (int m = 0; m < 2; m++)
#pragma unroll
                for (int n = 0; n < 4; n++)
                    mma_tf32(c1[m][n], a[m], b[n]);
        }
        __syncthreads();
    }

    // bias + relu -> fp16 pairs into H2 (overlays Xs; safe after sync above)
#pragma unroll
    for (int n = 0; n < 4; n++) {
        float2 bb = *(const float2*)(b1 + wn * 32 + n * 8 + 2 * tq);
        int colp = wn * 16 + n * 4 + tq;
#pragma unroll
        for (int m = 0; m < 2; m++) {
            int row = wm * 32 + m * 16 + g;
            float h0 = fmaxf(c1[m][n][0] + bb.x, 0.f);
            float h1 = fmaxf(c1[m][n][1] + bb.y, 0.f);
            float h2 = fmaxf(c1[m][n][2] + bb.x, 0.f);
            float h3 = fmaxf(c1[m][n][3] + bb.y, 0.f);
            __half2 p0 = __floats2half2_rn(h0, h1);
            __half2 p1 = __floats2half2_rn(h2, h3);
            H2[row    ][colp] = *(uint32_t*)&p0;
            H2[row + 8][colp] = *(uint32_t*)&p1;
        }
    }
    // W2 -> fp16 k-pair layout: W2p[k/2][n] = {W2[k][n], W2[k+1][n]}
#pragma unroll
    for (int l = 0; l < 8; l++) {
        int idx = t + l * 256;          // 0..2047
        int kp  = idx >> 6;             // 0..31
        int n   = idx & 63;
        float w0 = W2[(size_t)(2 * kp    ) * NCLS + n];
        float w1 = W2[(size_t)(2 * kp + 1) * NCLS + n];
        __half2 p = __floats2half2_rn(w0, w1);
        W2p[kp][n] = *(uint32_t*)&p;
    }
    __syncthreads();

    float c2[2][4][4];
#pragma unroll
    for (int m = 0; m < 2; m++)
#pragma unroll
        for (int n = 0; n < 4; n++)
#pragma unroll
            for (int i = 0; i < 4; i++) c2[m][n][i] = 0.0f;

#pragma unroll
    for (int ka = 0; ka < 4; ka++) {
        const int kp = ka * 8;          // half2-pair base (covers k = 16*ka .. +15)
        uint32_t a[2][4];
#pragma unroll
        for (int m = 0; m < 2; m++) {
            int row = wm * 32 + m * 16;
            a[m][0] = H2[row + g    ][kp + tq];
            a[m][1] = H2[row + g + 8][kp + tq];
            a[m][2] = H2[row + g    ][kp + tq + 4];
            a[m][3] = H2[row + g + 8][kp + tq + 4];
        }
        uint32_t b[4][2];
#pragma unroll
        for (int n = 0; n < 4; n++) {
            int col = wn * 32 + n * 8 + g;
            b[n][0] = W2p[kp + tq    ][col];
            b[n][1] = W2p[kp + tq + 4][col];
        }
#pragma unroll
        for (int m = 0; m < 2; m++)
#pragma unroll
            for (int n = 0; n < 4; n++)
                mma_f16(c2[m][n], a[m], b[n]);
    }

    // + b2, store logits as fp16
    __half2* lg2 = (__half2*)g_logits_h;
#pragma unroll
    for (int n = 0; n < 4; n++) {
        float2 bb = *(const float2*)(b2 + wn * 32 + n * 8 + 2 * tq);
        int colp = wn * 16 + n * 4 + tq;
#pragma unroll
        for (int m = 0; m < 2; m++) {
            int row = rb + wm * 32 + m * 16 + g;
            if (row < N_NODES)
                lg2[(size_t)row * 32 + colp] =
                    __floats2half2_rn(c2[m][n][0] + bb.x, c2[m][n][1] + bb.y);
            if (row + 8 < N_NODES)
                lg2[(size_t)(row + 8) * 32 + colp] =
                    __floats2half2_rn(c2[m][n][2] + bb.x, c2[m][n][3] + bb.y);
        }
    }
}

// ---------------------------------------------------------------------------
// Edge scatter: out[row] += val * logits[col]; 8 lanes/edge, fp16 gather,
// fp32 vectorized reduction.
// ---------------------------------------------------------------------------
__global__ __launch_bounds__(256) void edge_scatter(
    const int*   __restrict__ rows,
    const int*   __restrict__ cols,
    const float* __restrict__ vals,
    float*       __restrict__ out,
    int E)
{
    long long tid = (long long)blockIdx.x * 256 + threadIdx.x;
    int e = (int)(tid >> 3);
    if (e >= E) return;
    int j = (int)(tid & 7);

    int   r = __ldg(rows + e);
    int   c = __ldg(cols + e);
    float v = __ldg(vals + e);

    uint4 raw = *(const uint4*)(g_logits_h + (size_t)c * NCLS + j * 8);
    const __half2* hp = (const __half2*)&raw;
    float2 f0 = __half22float2(hp[0]);
    float2 f1 = __half22float2(hp[1]);
    float2 f2 = __half22float2(hp[2]);
    float2 f3 = __half22float2(hp[3]);

    float* dst = out + (size_t)r * NCLS + j * 8;
    asm volatile("red.global.add.v4.f32 [%0], {%1, %2, %3, %4};"
                 :: "l"(dst), "f"(f0.x * v), "f"(f0.y * v), "f"(f1.x * v), "f"(f1.y * v)
                 : "memory");
    asm volatile("red.global.add.v4.f32 [%0], {%1, %2, %3, %4};"
                 :: "l"(dst + 4), "f"(f2.x * v), "f"(f2.y * v), "f"(f3.x * v), "f"(f3.y * v)
                 : "memory");
}

// ---------------------------------------------------------------------------
extern "C" void kernel_launch(void* const* d_in, const int* in_sizes, int n_in,
                              void* d_out, int out_size)
{
    const float* X    = (const float*)d_in[0];
    const int*   erow = (const int*)  d_in[1];
    const int*   ecol = (const int*)  d_in[2];
    const float* ev   = (const float*)d_in[3];
    const float* W1   = (const float*)d_in[4];
    const float* b1   = (const float*)d_in[5];
    const float* W2   = (const float*)d_in[6];
    const float* b2   = (const float*)d_in[7];
    float* out = (float*)d_out;
    int E = in_sizes[1];

    cudaMemsetAsync(d_out, 0, (size_t)out_size * sizeof(float));

    mlp_mma<<<(N_NODES + BM - 1) / BM, 256>>>(X, W1, b1, W2, b2);

    long long threads = (long long)E * 8;
    int blocks = (int)((threads + 255) / 256);
    edge_scatter<<<blocks, 256>>>(erow, ecol, ev, out, E);
}